// round 5
// baseline (speedup 1.0000x reference)
#include <cuda_runtime.h>
#include <cstdint>

// Problem constants
#define BB   128
#define CIN  2
#define HIDC 150
#define AA   8
#define KIT  30
#define G    49
#define HP   51
#define GG   (G*G)      // 2401
#define HPHP (HP*HP)    // 2601
#define CPAD 160        // padded channel-last stride
#define VS   53         // HP+2 padded v tile

// ---------------- scratch (device globals; 16B-aligned for vector access) ----
__device__ __align__(16) float g_hT  [BB*GG*CPAD];   // conv1 out, channel-last
__device__ __align__(16) float g_h2T [BB*GG*CPAD];   // conv2 out, channel-last
__device__ __align__(16) float g_tr  [BB*AA*9*HPHP]; // trans -> softmaxed in place
__device__ __align__(16) float g_rew [BB*HPHP];
__device__ __align__(16) float g_wB2 [45*32*160];    // conv2 B tiles  [s][k][n]
__device__ __align__(16) float g_wBrt[45*32*80];     // convrt B tiles [s][k][n]

// ============================ PTX helpers ====================================
__device__ __forceinline__ uint32_t smem_u32(const void* p) {
    uint32_t a;
    asm("{ .reg .u64 t; cvta.to.shared.u64 t, %1; cvt.u32.u64 %0, t; }" : "=r"(a) : "l"(p));
    return a;
}
__device__ __forceinline__ float to_tf32(float x) {
    uint32_t u;
    asm("cvt.rna.tf32.f32 %0, %1;" : "=r"(u) : "f"(x));
    return __uint_as_float(u);
}
__device__ __forceinline__ void cpa16(uint32_t dst, const void* src, uint32_t sz) {
    asm volatile("cp.async.cg.shared.global [%0], [%1], 16, %2;"
                 :: "r"(dst), "l"(src), "r"(sz) : "memory");
}
#define CP_COMMIT() asm volatile("cp.async.commit_group;" ::: "memory")
#define CP_WAIT0()  asm volatile("cp.async.wait_group 0;" ::: "memory")
__device__ __forceinline__ void mma8(float* c, const uint32_t* a, const uint32_t* b) {
    asm volatile("mma.sync.aligned.m16n8k8.row.col.f32.tf32.tf32.f32 "
        "{%0,%1,%2,%3}, {%4,%5,%6,%7}, {%8,%9}, {%0,%1,%2,%3};"
        : "+f"(c[0]), "+f"(c[1]), "+f"(c[2]), "+f"(c[3])
        : "r"(a[0]), "r"(a[1]), "r"(a[2]), "r"(a[3]), "r"(b[0]), "r"(b[1]));
}

// ---------------- weight prep: build tf32 B tiles [s][k][n] ------------------
__global__ void prep_k(const float* __restrict__ h2w,
                       const float* __restrict__ rw,
                       const float* __restrict__ tw) {
    int i = blockIdx.x * blockDim.x + threadIdx.x;
    if (i < 45*32*160) {
        int n = i % 160, k = (i/160) % 32, s = i/(160*32);
        int tap = s/5, ci = (s%5)*32 + k;
        float v = 0.f;
        if (n < HIDC && ci < HIDC) v = h2w[(n*HIDC + ci)*9 + tap];
        g_wB2[i] = to_tf32(v);
    }
    if (i < 45*32*80) {
        int n = i % 80, k = (i/80) % 32, s = i/(80*32);
        int tap = s/5, ci = (s%5)*32 + k;
        float v = 0.f;
        if (ci < HIDC) {
            if (n == 0)      v = rw[ci*9 + tap];
            else if (n < 73) v = tw[((n-1)*HIDC + ci)*9 + tap];
        }
        g_wBrt[i] = to_tf32(v);
    }
}

// -------- conv1 fused with channel-last transpose: grid -> g_hT --------------
__global__ void conv1T_k(const float* __restrict__ gin,
                         const float* __restrict__ w,
                         const float* __restrict__ bias) {
    __shared__ float ws[HIDC*CIN*9];
    __shared__ float bs[HIDC];
    __shared__ __align__(16) float tile[32*164];
    int t = threadIdx.x;
    for (int i = t; i < HIDC*CIN*9; i += 256) ws[i] = w[i];
    for (int i = t; i < HIDC; i += 256) bs[i] = bias[i];
    __syncthreads();
    int pos0 = blockIdx.x * 32, b = blockIdx.y;
    int posi = t & 31, colane = t >> 5;
    int pos = pos0 + posi;
    bool okp = pos < GG;
    int y = okp ? pos / G : 0, x = okp ? pos % G : 0;
    float gv[CIN][9];
    #pragma unroll
    for (int ci = 0; ci < CIN; ci++)
        #pragma unroll
        for (int k = 0; k < 9; k++) {
            int r = y + k/3 - 1, c = x + k%3 - 1;
            gv[ci][k] = (okp && r >= 0 && r < G && c >= 0 && c < G)
                        ? gin[(b*CIN + ci)*GG + r*G + c] : 0.f;
        }
    #pragma unroll
    for (int j = 0; j < 19; j++) {
        int co = colane + 8*j;          // 0..151
        float out = 0.f;
        if (co < HIDC) {
            float acc = bs[co];
            #pragma unroll
            for (int ci = 0; ci < CIN; ci++)
                #pragma unroll
                for (int k = 0; k < 9; k++)
                    acc += gv[ci][k] * ws[(co*CIN + ci)*9 + k];
            out = to_tf32(fmaxf(acc, 0.f));
        }
        tile[posi*164 + co] = out;
    }
    if (t < 32)
        #pragma unroll
        for (int co = 152; co < CPAD; co++) tile[t*164 + co] = 0.f;
    __syncthreads();
    int p2 = t >> 3;
    if (pos0 + p2 < GG) {
        float4* op = (float4*)&g_hT[((size_t)(b*GG + pos0 + p2))*CPAD];
        #pragma unroll
        for (int i = 0; i < 5; i++) {
            int cq = (t & 7) + 8*i;
            op[cq] = *(float4*)&tile[p2*164 + cq*4];
        }
    }
}

// =============== tf32 mma.sync implicit-GEMM conv ============================
// D[pos 128, co NOUT_PAD] = sum over 45 chunks (9 taps x 5 ci-blocks of 32)
// MODE 0: conv2 (g_hT -> relu+bias -> g_h2T channel-last tf32), NFRAG=10 (N=160)
// MODE 1: convrt (g_h2T -> g_rew / g_tr), NFRAG=5 (N=80)
template<int NFRAG, int OW, int PADC, int PTOT, int MODE>
__global__ void __launch_bounds__(256, 2) mma_conv_k(const float* __restrict__ bias) {
    constexpr int NOUT_PAD = NFRAG * 16;
    constexpr int BPAD = NOUT_PAD + 8;
    constexpr int ASZ = 128 * 36;         // floats per A stage
    constexpr int BSZ = 32 * BPAD;        // floats per B stage
    constexpr int BQ  = 32 * NOUT_PAD / 4;
    extern __shared__ __align__(16) float sm[];
    float* biasS = sm + 2*ASZ + 2*BSZ;
    const float* inT = (MODE == 0) ? g_hT : g_h2T;
    const float* wB  = (MODE == 0) ? g_wB2 : g_wBrt;

    int t = threadIdx.x;
    int b = blockIdx.y, tile0 = blockIdx.x * 128;
    uint32_t smb = smem_u32(sm);

    if (MODE == 0) for (int i = t; i < HIDC; i += 256) biasS[i] = bias[i];

    // A-load invariants: thread covers rows m = (t>>3)+32i, 16B quad cq = t&7
    const int cq = t & 7;
    int yy[4], xx[4];
    uint32_t dA[4];
    #pragma unroll
    for (int i = 0; i < 4; i++) {
        int m = (t >> 3) + 32*i;
        int pos = tile0 + m;
        yy[i] = pos / OW;
        xx[i] = pos - yy[i]*OW;
        dA[i] = (uint32_t)(m*36 + cq*4) * 4;
    }
    const float* inB = inT + (size_t)b*GG*CPAD + cq*4;

    auto load_chunk = [&](int s, int stage) {
        int tap = s / 5, cc = s - tap*5;
        int dyp = tap/3 - PADC, dxp = tap%3 - PADC, ci0 = cc*32;
        uint32_t Ab = smb + (uint32_t)stage*ASZ*4;
        #pragma unroll
        for (int i = 0; i < 4; i++) {
            int ir = yy[i] + dyp, ic = xx[i] + dxp;
            bool ok = ((unsigned)ir < G) && ((unsigned)ic < G);
            const float* src = inB + (size_t)(ok ? (ir*G + ic) : 0)*CPAD + ci0;
            cpa16(Ab + dA[i], src, ok ? 16u : 0u);
        }
        uint32_t Bb = smb + (uint32_t)(2*ASZ + stage*BSZ)*4;
        const float* wsrc = wB + (size_t)s*32*NOUT_PAD;
        #pragma unroll
        for (int j = 0; j < (BQ + 255)/256; j++) {
            int q = t + 256*j;
            if (q < BQ) {
                int k = q / (NOUT_PAD/4), n4 = q - k*(NOUT_PAD/4);
                cpa16(Bb + (uint32_t)(k*BPAD + n4*4)*4, wsrc + q*4, 16u);
            }
        }
        CP_COMMIT();
    };

    const int lane = t & 31, wid = t >> 5;
    const int gid = lane >> 2, tig = lane & 3;
    const int m0w = (wid >> 1) * 32, n0w = (wid & 1) * NFRAG * 8;

    float c[2][NFRAG][4];
    #pragma unroll
    for (int mf = 0; mf < 2; mf++)
        #pragma unroll
        for (int nf = 0; nf < NFRAG; nf++)
            #pragma unroll
            for (int e = 0; e < 4; e++) c[mf][nf][e] = 0.f;

    load_chunk(0, 0);
    for (int s = 0; s < 45; s++) {
        int cur = s & 1;
        CP_WAIT0();
        __syncthreads();                    // data(s) visible; mma(s-1) done
        if (s < 44) load_chunk(s + 1, cur ^ 1);
        const float* As = sm + cur*ASZ;
        const float* Bs = sm + 2*ASZ + cur*BSZ;
        #pragma unroll
        for (int ks = 0; ks < 4; ks++) {
            int kc = ks*8 + tig;
            uint32_t a[2][4];
            #pragma unroll
            for (int mf = 0; mf < 2; mf++) {
                int r = m0w + mf*16 + gid;
                a[mf][0] = __float_as_uint(As[r*36 + kc]);
                a[mf][1] = __float_as_uint(As[(r+8)*36 + kc]);
                a[mf][2] = __float_as_uint(As[r*36 + kc + 4]);
                a[mf][3] = __float_as_uint(As[(r+8)*36 + kc + 4]);
            }
            // software-pipelined B fragments: load nf+2 while mma nf
            uint32_t bw[NFRAG][2];
            #pragma unroll
            for (int pre = 0; pre < 2 && pre < NFRAG; pre++) {
                int nc = n0w + pre*8 + gid;
                bw[pre][0] = __float_as_uint(Bs[kc*BPAD + nc]);
                bw[pre][1] = __float_as_uint(Bs[(kc+4)*BPAD + nc]);
            }
            #pragma unroll
            for (int nf = 0; nf < NFRAG; nf++) {
                if (nf + 2 < NFRAG) {
                    int nc = n0w + (nf+2)*8 + gid;
                    bw[nf+2][0] = __float_as_uint(Bs[kc*BPAD + nc]);
                    bw[nf+2][1] = __float_as_uint(Bs[(kc+4)*BPAD + nc]);
                }
                mma8(c[0][nf], a[0], bw[nf]);
                mma8(c[1][nf], a[1], bw[nf]);
            }
        }
        __syncthreads();                    // mma(s) done before load(s+2) overwrites
    }

    // ---- epilogue ----
    #pragma unroll
    for (int mf = 0; mf < 2; mf++) {
        #pragma unroll
        for (int rr = 0; rr < 2; rr++) {
            int pos = tile0 + m0w + mf*16 + gid + rr*8;
            if (pos >= PTOT) continue;
            if (MODE == 0) {
                float* op = &g_h2T[((size_t)(b*GG + pos))*CPAD];
                #pragma unroll
                for (int nf = 0; nf < NFRAG; nf++) {
                    int co = n0w + nf*8 + 2*tig;
                    float v0 = c[mf][nf][rr*2 + 0], v1 = c[mf][nf][rr*2 + 1];
                    float2 o;
                    o.x = (co   < HIDC) ? to_tf32(fmaxf(v0 + biasS[co],   0.f)) : 0.f;
                    o.y = (co+1 < HIDC) ? to_tf32(fmaxf(v1 + biasS[co+1], 0.f)) : 0.f;
                    *(float2*)&op[co] = o;
                }
            } else {
                #pragma unroll
                for (int nf = 0; nf < NFRAG; nf++) {
                    int co = n0w + nf*8 + 2*tig;
                    float v0 = c[mf][nf][rr*2 + 0], v1 = c[mf][nf][rr*2 + 1];
                    if (co == 0)      g_rew[b*HPHP + pos] = v0;
                    else if (co < 73) g_tr[((size_t)(b*72 + co - 1))*HPHP + pos] = v0;
                    if (co + 1 < 73)  g_tr[((size_t)(b*72 + co))*HPHP + pos] = v1;
                }
            }
        }
    }
}

// ---------------- softmax over 9 taps ---------------------------------------
__global__ void softmax_k() {
    int tid = blockIdx.x * blockDim.x + threadIdx.x;
    if (tid >= BB*AA*HPHP) return;
    int pos = tid % HPHP;
    int ba  = tid / HPHP;
    size_t base = (size_t)ba*9*HPHP + pos;
    float v[9];
    float m = -1e30f;
    #pragma unroll
    for (int k = 0; k < 9; k++) { v[k] = g_tr[base + (size_t)k*HPHP]; m = fmaxf(m, v[k]); }
    float s = 0.f;
    #pragma unroll
    for (int k = 0; k < 9; k++) { v[k] = expf(v[k] - m); s += v[k]; }
    float inv = 1.f / s;
    #pragma unroll
    for (int k = 0; k < 9; k++) g_tr[base + (size_t)k*HPHP] = v[k] * inv;
}

// -------- fused VI (30 iterations) + head, 1 CTA per batch -------------------
// smem: v ping-pong padded 53x53 (zero halo), q[A][HPHP], head weights.
#define VITHREADS 512
#define NPP 6                       // ceil(2601/512)
__global__ void __launch_bounds__(VITHREADS) vi_all_k(
        const float* __restrict__ a1w, const float* __restrict__ a1b,
        const float* __restrict__ a2w, const float* __restrict__ a2b,
        float* __restrict__ out) {
    extern __shared__ float vsm[];
    float* v0 = vsm;                       // VS*VS
    float* v1 = v0 + VS*VS;
    float* qs = v1 + VS*VS;                // AA*HPHP, layout [a][pos]
    float* a1s = qs + AA*HPHP;             // HIDC*AA
    float* a2s = a1s + HIDC*AA;            // AA*HIDC
    float* b1s = a2s + AA*HIDC;            // HIDC
    float* b2s = b1s + HIDC;               // AA

    int b = blockIdx.x, t = threadIdx.x;
    for (int i = t; i < HIDC*AA; i += VITHREADS) { a1s[i] = a1w[i]; a2s[i] = a2w[i]; }
    for (int i = t; i < HIDC; i += VITHREADS) b1s[i] = a1b[i];
    if (t < AA) b2s[t] = a2b[t];
    for (int i = t; i < VS*VS; i += VITHREADS) { v0[i] = 0.f; v1[i] = 0.f; }

    // per-thread position set + reward regs; v init = reward (VI step 0)
    float rr[NPP];
    int voff[NPP];
    #pragma unroll
    for (int pp = 0; pp < NPP; pp++) {
        int pos = t + pp*VITHREADS;
        if (pos < HPHP) {
            int y = pos / HP, x = pos - y*HP;
            voff[pp] = y*VS + x;
            rr[pp] = g_rew[b*HPHP + pos];
        } else { voff[pp] = 0; rr[pp] = 0.f; }
    }
    __syncthreads();
    #pragma unroll
    for (int pp = 0; pp < NPP; pp++) {
        int pos = t + pp*VITHREADS;
        if (pos < HPHP) v0[voff[pp] + VS + 1] = rr[pp];
    }
    __syncthreads();

    const float* trb = g_tr + (size_t)b*72*HPHP;
    float* vc = v0;
    float* vn = v1;
    for (int it = 1; it < KIT; it++) {
        bool last = (it == KIT - 1);
        #pragma unroll
        for (int pp = 0; pp < NPP; pp++) {
            int pos = t + pp*VITHREADS;
            if (pos >= HPHP) continue;
            int vo = voff[pp];
            float p[9];
            #pragma unroll
            for (int k = 0; k < 9; k++) p[k] = vc[vo + (k/3)*VS + (k%3)];
            const float* tp = trb + pos;
            float vmax = -1e30f;
            #pragma unroll
            for (int a = 0; a < AA; a++) {
                float q = rr[pp];
                #pragma unroll
                for (int k = 0; k < 9; k++)
                    q = fmaf(tp[(size_t)(a*9 + k)*HPHP], p[k], q);
                if (last) qs[a*HPHP + pos] = q;
                vmax = fmaxf(vmax, q);
            }
            if (!last) vn[vo + VS + 1] = vmax;
        }
        __syncthreads();
        float* tmp = vc; vc = vn; vn = tmp;
    }

    // ---- head: q[:, :49, :49] -> 150 -> 8 ----
    for (int pos = t; pos < GG; pos += VITHREADS) {
        int y = pos / G, x = pos - y*G;
        int pos51 = y*HP + x;
        float qv[AA];
        #pragma unroll
        for (int a = 0; a < AA; a++) qv[a] = qs[a*HPHP + pos51];
        float lg[AA];
        #pragma unroll
        for (int a = 0; a < AA; a++) lg[a] = 0.f;
        for (int cch = 0; cch < HIDC; cch++) {
            float m = b1s[cch];
            #pragma unroll
            for (int a = 0; a < AA; a++) m = fmaf(qv[a], a1s[cch*AA + a], m);
            m = fmaxf(m, 0.f);
            #pragma unroll
            for (int a = 0; a < AA; a++) lg[a] = fmaf(m, a2s[a*HIDC + cch], lg[a]);
        }
        #pragma unroll
        for (int a = 0; a < AA; a++) out[(b*AA + a)*GG + pos] = lg[a] + b2s[a];
    }
}

// ---------------- launch -----------------------------------------------------
extern "C" void kernel_launch(void* const* d_in, const int* in_sizes, int n_in,
                              void* d_out, int out_size) {
    const float* grid = (const float*)d_in[0];
    const float* h1w = (const float*)d_in[3];
    const float* h1b = (const float*)d_in[4];
    const float* h2w = (const float*)d_in[5];
    const float* h2b = (const float*)d_in[6];
    const float* rw  = (const float*)d_in[7];
    const float* tw  = (const float*)d_in[8];
    const float* a1w = (const float*)d_in[9];
    const float* a1b = (const float*)d_in[10];
    const float* a2w = (const float*)d_in[11];
    const float* a2b = (const float*)d_in[12];
    float* out = (float*)d_out;

    const int SMEM2  = (2*128*36 + 2*32*168 + 160) * 4;   // 80512 B
    const int SMEMRT = (2*128*36 + 2*32*88) * 4;          // 59392 B
    const int SMEMVI = (2*VS*VS + AA*HPHP + HIDC*AA*2 + HIDC + AA) * 4;  // ~115.9 KB
    cudaFuncSetAttribute(mma_conv_k<10, G, 1, GG, 0>,
                         cudaFuncAttributeMaxDynamicSharedMemorySize, SMEM2);
    cudaFuncSetAttribute(mma_conv_k<5, HP, 2, HPHP, 1>,
                         cudaFuncAttributeMaxDynamicSharedMemorySize, SMEMRT);
    cudaFuncSetAttribute(vi_all_k,
                         cudaFuncAttributeMaxDynamicSharedMemorySize, SMEMVI);

    prep_k<<<(45*32*160 + 255)/256, 256>>>(h2w, rw, tw);
    conv1T_k<<<dim3((GG + 31)/32, BB), 256>>>(grid, h1w, h1b);
    mma_conv_k<10, G, 1, GG, 0><<<dim3((GG + 127)/128, BB), 256, SMEM2>>>(h2b);
    mma_conv_k<5, HP, 2, HPHP, 1><<<dim3((HPHP + 127)/128, BB), 256, SMEMRT>>>(nullptr);
    softmax_k<<<(BB*AA*HPHP + 255)/256, 256>>>();
    vi_all_k<<<BB, VITHREADS, SMEMVI>>>(a1w, a1b, a2w, a2b, out);
}